// round 5
// baseline (speedup 1.0000x reference)
#include <cuda_runtime.h>
#include <cstdint>
#include <cstddef>

#define T_STEPS 2048
#define BATCH   64
#define IN_DIM  256
#define HID     512
#define BH      (BATCH * HID)

__device__ __align__(128) float g_xproj[(size_t)T_STEPS * BH]; // 256 MiB

// ---------------- Phase A: x_proj GEMM (unchanged) ---------------------------
#define GBM 64
#define GBN 64
#define GBK 32
#define GTM 4
#define GTN 4

__global__ __launch_bounds__(256) void xproj_gemm_kernel(
    const float* __restrict__ A, const float* __restrict__ B)
{
    __shared__ float As[GBK][GBM];
    __shared__ float Bs[GBK][GBN];
    const int tid = threadIdx.x;
    const int tx = tid % 16, ty = tid / 16;
    const size_t mBase = (size_t)blockIdx.y * GBM;
    const int    nBase = blockIdx.x * GBN;

    float acc[GTM][GTN];
#pragma unroll
    for (int i = 0; i < GTM; i++)
#pragma unroll
        for (int j = 0; j < GTN; j++) acc[i][j] = 0.0f;

    for (int kt = 0; kt < IN_DIM; kt += GBK) {
#pragma unroll
        for (int s = 0; s < 2; s++) {
            int row = tid / 8 + s * 32;
            int k4  = (tid % 8) * 4;
            float4 v = *(const float4*)&A[(mBase + row) * IN_DIM + kt + k4];
            As[k4 + 0][row] = v.x; As[k4 + 1][row] = v.y;
            As[k4 + 2][row] = v.z; As[k4 + 3][row] = v.w;
        }
#pragma unroll
        for (int s = 0; s < 2; s++) {
            int row = tid / 16 + s * 16;
            int n4  = (tid % 16) * 4;
            *(float4*)&Bs[row][n4] =
                *(const float4*)&B[(size_t)(kt + row) * HID + nBase + n4];
        }
        __syncthreads();
#pragma unroll
        for (int k = 0; k < GBK; k++) {
            float a[GTM], b[GTN];
            *(float4*)a = *(const float4*)&As[k][ty * GTM];
            *(float4*)b = *(const float4*)&Bs[k][tx * GTN];
#pragma unroll
            for (int i = 0; i < GTM; i++)
#pragma unroll
                for (int j = 0; j < GTN; j++)
                    acc[i][j] += a[i] * b[j];
        }
        __syncthreads();
    }
#pragma unroll
    for (int i = 0; i < GTM; i++) {
        size_t row = mBase + ty * GTM + i;
        *(float4*)&g_xproj[row * HID + nBase + tx * GTN] =
            make_float4(acc[i][0], acc[i][1], acc[i][2], acc[i][3]);
    }
}

// ---------------- Phase B: cluster scan, 512 thr/CTA, b64 st.async ----------
#define CLS  8
#define BPC  4
#define JPC  64
#define NKC  16
#define KC   (HID / NKC)      // 32
#define HPAD 516

#define WS_OFF   0
#define WS_FLOATS (HID * JPC)                 // 32768
#define HS_OFF   (WS_OFF + WS_FLOATS)
#define HS_FLOATS (2 * BPC * HPAD)            // 4128
#define RED_OFF  (HS_OFF + HS_FLOATS)
#define RED_FLOATS (NKC * 256)                // 4096
#define MB_OFF   (RED_OFF + RED_FLOATS)
#define SCAN_SMEM_BYTES  ((MB_OFF + 8) * 4)

#define TX_BYTES_PER_PHASE (CLS * 256 * 4)    // 8192 B into each CTA per phase

__device__ __forceinline__ void cluster_sync_() {
    asm volatile("barrier.cluster.arrive.aligned;" ::: "memory");
    asm volatile("barrier.cluster.wait.aligned;"   ::: "memory");
}
__device__ __forceinline__ void mbar_init_(unsigned a, unsigned cnt) {
    asm volatile("mbarrier.init.shared.b64 [%0], %1;" :: "r"(a), "r"(cnt) : "memory");
}
__device__ __forceinline__ void mbar_expect_tx_(unsigned a, unsigned bytes) {
    asm volatile("mbarrier.arrive.expect_tx.shared.b64 _, [%0], %1;"
                 :: "r"(a), "r"(bytes) : "memory");
}
__device__ __forceinline__ void mbar_wait_(unsigned a, unsigned parity) {
    unsigned done;
    asm volatile(
        "{\n\t.reg .pred p;\n\t"
        "mbarrier.try_wait.parity.acquire.cta.shared::cta.b64 p, [%1], %2;\n\t"
        "selp.b32 %0, 1, 0, p;\n\t}"
        : "=r"(done) : "r"(a), "r"(parity) : "memory");
    if (!done) {
        asm volatile(
            "{\n\t.reg .pred P1;\n\t"
            "WL_%=:\n\t"
            "mbarrier.try_wait.parity.acquire.cta.shared::cta.b64 P1, [%0], %1, 0x989680;\n\t"
            "@P1 bra.uni WD_%=;\n\t"
            "bra.uni WL_%=;\n\t"
            "WD_%=:\n\t}"
            :: "r"(a), "r"(parity) : "memory");
    }
}
__device__ __forceinline__ void st_async_u64_(unsigned raddr, unsigned long long v,
                                              unsigned rmbar) {
    asm volatile(
        "st.async.shared::cluster.mbarrier::complete_tx::bytes.b64 [%0], %1, [%2];"
        :: "r"(raddr), "l"(v), "r"(rmbar) : "memory");
}
__device__ __forceinline__ unsigned long long fma2_(
    unsigned long long a, unsigned long long b, unsigned long long c) {
    unsigned long long d;
    asm("fma.rn.f32x2 %0, %1, %2, %3;" : "=l"(d) : "l"(a), "l"(b), "l"(c));
    return d;
}
__device__ __forceinline__ unsigned long long pack2_(float x) {
    unsigned long long d;
    asm("mov.b64 %0, {%1, %1};" : "=l"(d) : "r"(__float_as_int(x)));
    return d;
}
__device__ __forceinline__ unsigned long long packab_(float lo, float hi) {
    unsigned long long d;
    asm("mov.b64 %0, {%1, %2};" : "=l"(d)
        : "r"(__float_as_int(lo)), "r"(__float_as_int(hi)));
    return d;
}

__global__ __launch_bounds__(512, 1) __cluster_dims__(CLS, 1, 1)
void rnn_scan_kernel(const float* __restrict__ w_rec,
                     float* __restrict__ out, int write_last)
{
    extern __shared__ float smem[];
    float* ws  = smem + WS_OFF;   // [HID][JPC]
    float* hs  = smem + HS_OFF;   // [2][BPC][HPAD]
    float* red = smem + RED_OFF;  // [NKC][256]

    const int tid  = threadIdx.x;
    const int rank = blockIdx.x & (CLS - 1);
    const int b0   = (blockIdx.x >> 3) * BPC;
    const int j0   = rank * JPC;

    const int kc = tid >> 5;      // 0..15 k-chunk (constant per warp)
    const int jg = tid & 31;      // 0..31 j-pair
    const int ob = (tid >> 6) & 3;// output batch (tid<256)
    const int oj = tid & 63;      // output column

    // ---- prologue ----
    {
        const float4* wsrc = (const float4*)w_rec;
        float4* wdst = (float4*)ws;
        for (int i = tid; i < HID * (JPC / 4); i += 512) {
            int row = i >> 4, c4 = i & 15;
            wdst[row * 16 + c4] = wsrc[row * (HID / 4) + (j0 >> 2) + c4];
        }
        for (int i = tid; i < HS_FLOATS; i += 512) hs[i] = 0.0f;
        if (tid == 0) {
            unsigned mb = (unsigned)__cvta_generic_to_shared(smem + MB_OFF);
            mbar_init_(mb, 1);
            mbar_init_(mb + 8, 1);
        }
    }
    __syncthreads();
    cluster_sync_();

    const unsigned hs_loc = (unsigned)__cvta_generic_to_shared(hs);
    const unsigned mb_loc = (unsigned)__cvta_generic_to_shared(smem + MB_OFF);
    unsigned peer_hs[CLS], peer_mb[CLS];
#pragma unroll
    for (int r = 0; r < CLS; r++) {
        asm("mapa.shared::cluster.u32 %0, %1, %2;" : "=r"(peer_hs[r]) : "r"(hs_loc), "r"(r));
        asm("mapa.shared::cluster.u32 %0, %1, %2;" : "=r"(peer_mb[r]) : "r"(mb_loc), "r"(r));
    }

    const float* wrow = ws + (kc * KC) * JPC + jg * 2;
    const size_t xbase = (size_t)(b0 + ob) * HID + j0 + oj;
    // b64 destination: pair (oj&~1, oj|1)
    const unsigned st_off_base = (unsigned)((ob * HPAD + j0 + (oj & ~1)) * 4);
    const int rhalf = (oj & 1) ? 4 : 0;   // even threads -> ranks 0-3, odd -> 4-7

    int par0 = 0, par1 = 0;

#pragma unroll 1
    for (int t = 0; t < T_STEPS; t++) {
        const int q  = t & 1;
        const int qn = q ^ 1;

        float xv = (tid < 256) ? __ldg(&g_xproj[(size_t)t * BH + xbase]) : 0.0f;

        if (t > 0) {
            if (q == 0) { mbar_wait_(mb_loc,     par0); par0 ^= 1; }
            else        { mbar_wait_(mb_loc + 8, par1); par1 ^= 1; }
        }
        if (tid == 0 && t < T_STEPS - 1)
            mbar_expect_tx_(mb_loc + (unsigned)qn * 8, TX_BYTES_PER_PHASE);

        // ---- split-K partials: each thread: 2 j-cols x 4 b x 32 k ----
        const float* hp = hs + q * BPC * HPAD + kc * KC;

        unsigned long long acc[BPC] = {0ull, 0ull, 0ull, 0ull};
#pragma unroll
        for (int ki = 0; ki < KC; ki += 4) {
            unsigned long long w0 = *(const unsigned long long*)(wrow + (ki + 0) * JPC);
            unsigned long long w1 = *(const unsigned long long*)(wrow + (ki + 1) * JPC);
            unsigned long long w2 = *(const unsigned long long*)(wrow + (ki + 2) * JPC);
            unsigned long long w3 = *(const unsigned long long*)(wrow + (ki + 3) * JPC);
#pragma unroll
            for (int b = 0; b < BPC; b++) {
                float4 h4 = *(const float4*)(hp + b * HPAD + ki);
                acc[b] = fma2_(pack2_(h4.x), w0, acc[b]);
                acc[b] = fma2_(pack2_(h4.y), w1, acc[b]);
                acc[b] = fma2_(pack2_(h4.z), w2, acc[b]);
                acc[b] = fma2_(pack2_(h4.w), w3, acc[b]);
            }
        }
#pragma unroll
        for (int b = 0; b < BPC; b++)
            *(float2*)&red[kc * 256 + b * 64 + jg * 2] = *(float2*)&acc[b];
        __syncthreads();

        if (tid < 256) {
            float s = 0.0f;
#pragma unroll
            for (int c = 0; c < NKC; c++) s += red[c * 256 + tid];
            float hn = tanhf(xv + s);

            out[(size_t)t * BH + xbase] = hn;
            if (write_last && t == T_STEPS - 1)
                out[(size_t)T_STEPS * BH + xbase] = hn;

            if (t < T_STEPS - 1) {
                float hpart = __shfl_xor_sync(0xFFFFFFFFu, hn, 1);
                unsigned long long pkt = (oj & 1) ? packab_(hpart, hn)
                                                  : packab_(hn, hpart);
                unsigned doff = (unsigned)(qn * BPC * HPAD * 4) + st_off_base;
                unsigned moff = (unsigned)qn * 8;
#pragma unroll
                for (int i = 0; i < 4; i++) {
                    int r = rhalf + ((rank + i) & 3);
                    st_async_u64_(peer_hs[r] + doff, pkt, peer_mb[r] + moff);
                }
            }
        }
    }
    cluster_sync_();
}

// ---------------- launch ----------------------------------------------------
extern "C" void kernel_launch(void* const* d_in, const int* in_sizes, int n_in,
                              void* d_out, int out_size)
{
    const float* input = (const float*)d_in[0];
    const float* w_in  = (const float*)d_in[1];
    const float* w_rec = (const float*)d_in[2];
    float* out = (float*)d_out;

    int write_last =
        ((size_t)out_size >= (size_t)T_STEPS * BH + (size_t)BH) ? 1 : 0;

    cudaFuncSetAttribute(rnn_scan_kernel,
                         cudaFuncAttributeMaxDynamicSharedMemorySize,
                         SCAN_SMEM_BYTES);

    dim3 grid(HID / GBN, (T_STEPS * BATCH) / GBM);
    xproj_gemm_kernel<<<grid, 256>>>(input, w_in);

    rnn_scan_kernel<<<BATCH / BPC * CLS, 512, SCAN_SMEM_BYTES>>>(
        w_rec, out, write_last);
}

// round 7
// speedup vs baseline: 1.0673x; 1.0673x over previous
#include <cuda_runtime.h>
#include <cstdint>
#include <cstddef>

#define T_STEPS 2048
#define BATCH   64
#define IN_DIM  256
#define HID     512
#define BH      (BATCH * HID)

__device__ __align__(128) float g_xproj[(size_t)T_STEPS * BH]; // 256 MiB

// ---------------- Phase A: x_proj GEMM (unchanged, known-good) --------------
#define GBM 64
#define GBN 64
#define GBK 32
#define GTM 4
#define GTN 4

__global__ __launch_bounds__(256) void xproj_gemm_kernel(
    const float* __restrict__ A, const float* __restrict__ B)
{
    __shared__ float As[GBK][GBM];
    __shared__ float Bs[GBK][GBN];
    const int tid = threadIdx.x;
    const int tx = tid % 16, ty = tid / 16;
    const size_t mBase = (size_t)blockIdx.y * GBM;
    const int    nBase = blockIdx.x * GBN;

    float acc[GTM][GTN];
#pragma unroll
    for (int i = 0; i < GTM; i++)
#pragma unroll
        for (int j = 0; j < GTN; j++) acc[i][j] = 0.0f;

    for (int kt = 0; kt < IN_DIM; kt += GBK) {
#pragma unroll
        for (int s = 0; s < 2; s++) {
            int row = tid / 8 + s * 32;
            int k4  = (tid % 8) * 4;
            float4 v = *(const float4*)&A[(mBase + row) * IN_DIM + kt + k4];
            As[k4 + 0][row] = v.x; As[k4 + 1][row] = v.y;
            As[k4 + 2][row] = v.z; As[k4 + 3][row] = v.w;
        }
#pragma unroll
        for (int s = 0; s < 2; s++) {
            int row = tid / 16 + s * 16;
            int n4  = (tid % 16) * 4;
            *(float4*)&Bs[row][n4] =
                *(const float4*)&B[(size_t)(kt + row) * HID + nBase + n4];
        }
        __syncthreads();
#pragma unroll
        for (int k = 0; k < GBK; k++) {
            float a[GTM], b[GTN];
            *(float4*)a = *(const float4*)&As[k][ty * GTM];
            *(float4*)b = *(const float4*)&Bs[k][tx * GTN];
#pragma unroll
            for (int i = 0; i < GTM; i++)
#pragma unroll
                for (int j = 0; j < GTN; j++)
                    acc[i][j] += a[i] * b[j];
        }
        __syncthreads();
    }
#pragma unroll
    for (int i = 0; i < GTM; i++) {
        size_t row = mBase + ty * GTM + i;
        *(float4*)&g_xproj[row * HID + nBase + tx * GTN] =
            make_float4(acc[i][0], acc[i][1], acc[i][2], acc[i][3]);
    }
}

// ---------------- Phase B: reg-resident-w cluster scan ----------------------
#define CLS  8
#define BPC  4
#define TX_BYTES_PER_PHASE (CLS * 256 * 4)   // 8192

typedef unsigned long long ull;

__device__ __forceinline__ void cluster_sync_() {
    asm volatile("barrier.cluster.arrive.aligned;" ::: "memory");
    asm volatile("barrier.cluster.wait.aligned;"   ::: "memory");
}
__device__ __forceinline__ void mbar_init_(unsigned a, unsigned cnt) {
    asm volatile("mbarrier.init.shared.b64 [%0], %1;" :: "r"(a), "r"(cnt) : "memory");
}
__device__ __forceinline__ void mbar_expect_tx_(unsigned a, unsigned bytes) {
    asm volatile("mbarrier.arrive.expect_tx.shared.b64 _, [%0], %1;"
                 :: "r"(a), "r"(bytes) : "memory");
}
__device__ __forceinline__ void mbar_wait_(unsigned a, unsigned parity) {
    unsigned done;
    asm volatile(
        "{\n\t.reg .pred p;\n\t"
        "mbarrier.try_wait.parity.acquire.cta.shared::cta.b64 p, [%1], %2;\n\t"
        "selp.b32 %0, 1, 0, p;\n\t}"
        : "=r"(done) : "r"(a), "r"(parity) : "memory");
    if (!done) {
        asm volatile(
            "{\n\t.reg .pred P1;\n\t"
            "WL_%=:\n\t"
            "mbarrier.try_wait.parity.acquire.cta.shared::cta.b64 P1, [%0], %1, 0x989680;\n\t"
            "@P1 bra.uni WD_%=;\n\t"
            "bra.uni WL_%=;\n\t"
            "WD_%=:\n\t}"
            :: "r"(a), "r"(parity) : "memory");
    }
}
__device__ __forceinline__ void st_async_u64_(unsigned raddr, ull v, unsigned rmbar) {
    asm volatile(
        "st.async.shared::cluster.mbarrier::complete_tx::bytes.b64 [%0], %1, [%2];"
        :: "r"(raddr), "l"(v), "r"(rmbar) : "memory");
}
__device__ __forceinline__ ull fma2_(ull a, ull b, ull c) {
    ull d;
    asm("fma.rn.f32x2 %0, %1, %2, %3;" : "=l"(d) : "l"(a), "l"(b), "l"(c));
    return d;
}
__device__ __forceinline__ ull addx2_(ull a, ull b) {
    ull d;
    asm("add.rn.f32x2 %0, %1, %2;" : "=l"(d) : "l"(a), "l"(b));
    return d;
}
__device__ __forceinline__ ull pack2_(float x) {
    ull d;
    asm("mov.b64 %0, {%1, %1};" : "=l"(d) : "r"(__float_as_int(x)));
    return d;
}
__device__ __forceinline__ ull packab_(float lo, float hi) {
    ull d;
    asm("mov.b64 %0, {%1, %2};" : "=l"(d)
        : "r"(__float_as_int(lo)), "r"(__float_as_int(hi)));
    return d;
}

__global__ __launch_bounds__(512, 1) __cluster_dims__(CLS, 1, 1)
void rnn_scan_kernel(const float* __restrict__ w_rec,
                     float* __restrict__ out, int write_last)
{
    __shared__ float hs[2][BPC][HID];            // 16 KB
    __shared__ __align__(16) ull mbars[2];

    const int tid  = threadIdx.x;
    const int lane = tid & 31;
    const int jw   = tid >> 5;                   // warp id 0..15
    const int rank = blockIdx.x & (CLS - 1);
    const int bg0  = (blockIdx.x >> 3) * BPC;
    const int j0   = rank * 64;
    const int colw = j0 + jw * 4;                // warp's 4 columns

    // ---- prologue ----
    for (int i = tid; i < 2 * BPC * HID; i += 512) ((float*)hs)[i] = 0.0f;
    if (tid == 0) {
        unsigned mb = (unsigned)__cvta_generic_to_shared(mbars);
        mbar_init_(mb, 1);
        mbar_init_(mb + 8, 1);
    }

    // w[seg][m][cp]: w_rec[k][colw..colw+3], k = seg*128 + lane*4 + m
    ull w_[4][4][2];
#pragma unroll
    for (int seg = 0; seg < 4; seg++)
#pragma unroll
        for (int m = 0; m < 4; m++) {
            int k = seg * 128 + lane * 4 + m;
            float4 wv = *(const float4*)&w_rec[(size_t)k * HID + colw];
            w_[seg][m][0] = packab_(wv.x, wv.y);
            w_[seg][m][1] = packab_(wv.z, wv.w);
        }

    __syncthreads();
    cluster_sync_();

    const unsigned hs_loc = (unsigned)__cvta_generic_to_shared(hs);
    const unsigned mb_loc = (unsigned)__cvta_generic_to_shared(mbars);
    unsigned peer_hs[CLS], peer_mb[CLS];
#pragma unroll
    for (int r = 0; r < CLS; r++) {
        asm("mapa.shared::cluster.u32 %0, %1, %2;" : "=r"(peer_hs[r]) : "r"(hs_loc), "r"(r));
        asm("mapa.shared::cluster.u32 %0, %1, %2;" : "=r"(peer_mb[r]) : "r"(mb_loc), "r"(r));
    }

    // output identity: id = lane bits [4:1]
    const int id  = (lane >> 1) & 15;
    const int obt = id >> 2;
    const int ocl = colw + (id & 3);
    const size_t obase = (size_t)(bg0 + obt) * HID + ocl;
    const bool sender = ((lane & 3) == 0);
    const unsigned snd_off = (unsigned)((obt * HID + colw + (id & 2)) * 4);

    const int b4 = (lane >> 4) & 1;
    const int b3 = (lane >> 3) & 1;
    const int b2 = (lane >> 2) & 1;
    const int b1 = (lane >> 1) & 1;

    int par0 = 0, par1 = 0;

#pragma unroll 1
    for (int t = 0; t < T_STEPS; t++) {
        const int q  = t & 1;
        const int qn = q ^ 1;

        float xv = __ldg(&g_xproj[(size_t)t * BH + obase]);

        if (t > 0) {
            if (q == 0) { mbar_wait_(mb_loc,     par0); par0 ^= 1; }
            else        { mbar_wait_(mb_loc + 8, par1); par1 ^= 1; }
        }
        if (tid == 0 && t < T_STEPS - 1)
            mbar_expect_tx_(mb_loc + (unsigned)qn * 8, TX_BYTES_PER_PHASE);

        // ---- 128 FFMA2 over this lane's 16 k-values ----
        ull acc[BPC][2];
#pragma unroll
        for (int b = 0; b < BPC; b++) { acc[b][0] = 0ull; acc[b][1] = 0ull; }

#pragma unroll
        for (int seg = 0; seg < 4; seg++) {
            float4 h4[BPC];
#pragma unroll
            for (int b = 0; b < BPC; b++)
                h4[b] = *(const float4*)&hs[q][b][seg * 128 + lane * 4];
#pragma unroll
            for (int m = 0; m < 4; m++) {
#pragma unroll
                for (int b = 0; b < BPC; b++) {
                    float hv = (m == 0) ? h4[b].x : (m == 1) ? h4[b].y
                             : (m == 2) ? h4[b].z : h4[b].w;
                    ull hh = pack2_(hv);
                    acc[b][0] = fma2_(hh, w_[seg][m][0], acc[b][0]);
                    acc[b][1] = fma2_(hh, w_[seg][m][1], acc[b][1]);
                }
            }
        }

        // ---- warp reduce-scatter (FIXED: exchange the complement) ----
        // r1 (xor16): keep batches {2b4, 2b4+1}; send the other batch pair
        ull k00 = b4 ? acc[2][0] : acc[0][0];
        ull s00 = b4 ? acc[0][0] : acc[2][0];
        ull k01 = b4 ? acc[2][1] : acc[0][1];
        ull s01 = b4 ? acc[0][1] : acc[2][1];
        ull k10 = b4 ? acc[3][0] : acc[1][0];
        ull s10 = b4 ? acc[1][0] : acc[3][0];
        ull k11 = b4 ? acc[3][1] : acc[1][1];
        ull s11 = b4 ? acc[1][1] : acc[3][1];
        k00 = addx2_(k00, __shfl_xor_sync(0xffffffffu, s00, 16));
        k01 = addx2_(k01, __shfl_xor_sync(0xffffffffu, s01, 16));
        k10 = addx2_(k10, __shfl_xor_sync(0xffffffffu, s10, 16));
        k11 = addx2_(k11, __shfl_xor_sync(0xffffffffu, s11, 16));
        // r2 (xor8): keep batch b3 within pair; send the other
        ull u0k = b3 ? k10 : k00;
        ull u0s = b3 ? k00 : k10;
        ull u1k = b3 ? k11 : k01;
        ull u1s = b3 ? k01 : k11;
        ull u0 = addx2_(u0k, __shfl_xor_sync(0xffffffffu, u0s, 8));
        ull u1 = addx2_(u1k, __shfl_xor_sync(0xffffffffu, u1s, 8));
        // r3 (xor4): keep col-pair b2; send the other
        ull zk = b2 ? u1 : u0;
        ull zs = b2 ? u0 : u1;
        ull z  = addx2_(zk, __shfl_xor_sync(0xffffffffu, zs, 4));
        // r4 (xor2): same component of partner's register (partner keeps other)
        float2 zf = *(float2*)&z;
        ull zp = __shfl_xor_sync(0xffffffffu, z, 2);
        float2 pf = *(float2*)&zp;
        float s = (b1 ? zf.y : zf.x) + (b1 ? pf.y : pf.x);
        // r5 (xor1): final pairwise sum (lanes l, l^1 share an output)
        s += __shfl_xor_sync(0xffffffffu, s, 1);

        float hn = tanhf(xv + s);

        // pack (id, id+1): partner scalar sits at lane^2
        float hp2 = __shfl_xor_sync(0xffffffffu, hn, 2);
        ull pkt = packab_(hn, hp2);

        if (sender) {
            *(float2*)&out[(size_t)t * BH + obase] = *(float2*)&pkt;
            if (write_last && t == T_STEPS - 1)
                *(float2*)&out[(size_t)T_STEPS * BH + obase] = *(float2*)&pkt;

            if (t < T_STEPS - 1) {
                unsigned doff = (unsigned)(qn * BPC * HID * 4) + snd_off;
                unsigned moff = (unsigned)qn * 8;
#pragma unroll
                for (int i = 0; i < CLS; i++) {
                    int r = (jw + i) & (CLS - 1);
                    st_async_u64_(peer_hs[r] + doff, pkt, peer_mb[r] + moff);
                }
            }
        }
    }
    cluster_sync_();
}

// ---------------- launch ----------------------------------------------------
extern "C" void kernel_launch(void* const* d_in, const int* in_sizes, int n_in,
                              void* d_out, int out_size)
{
    const float* input = (const float*)d_in[0];
    const float* w_in  = (const float*)d_in[1];
    const float* w_rec = (const float*)d_in[2];
    float* out = (float*)d_out;

    int write_last =
        ((size_t)out_size >= (size_t)T_STEPS * BH + (size_t)BH) ? 1 : 0;

    dim3 grid(HID / GBN, (T_STEPS * BATCH) / GBM);
    xproj_gemm_kernel<<<grid, 256>>>(input, w_in);

    rnn_scan_kernel<<<BATCH / BPC * CLS, 512>>>(w_rec, out, write_last);
}

// round 8
// speedup vs baseline: 1.0832x; 1.0149x over previous
#include <cuda_runtime.h>
#include <cstdint>
#include <cstddef>

// Problem constants
#define T_STEPS 2048
#define BATCH   64
#define IN_DIM  256
#define HID     512
#define BH      (BATCH * HID)

// ---------------- Fused cluster scan (x-proj folded in) ---------------------
// 16 independent clusters of 8 CTAs, 256 threads each (R3 structure).
// CTA r owns hidden cols [64r,64r+64) x 4 batches; w_rec slice in smem,
// w_in slice in registers. Per step: thread (kc,jg) computes split-K partials
// of h@w_rec over 32 k AND x@w_in over 16 i into the same accumulators;
// one smem reduction; tanh; b32 st.async broadcast to 8 ranks with
// mbarrier transaction counting (double-buffered).
#define CLS  8
#define BPC  4
#define JPC  64
#define NKC  16
#define KC   (HID / NKC)      // 32
#define IC   (IN_DIM / NKC)   // 16 input rows per chunk
#define HPAD 516

// smem layout (float offsets)
#define WS_OFF   0
#define WS_FLOATS (HID * JPC)                 // 32768 (128 KB)
#define HS_OFF   (WS_OFF + WS_FLOATS)
#define HS_FLOATS (2 * BPC * HPAD)            // 4128
#define RED_OFF  (HS_OFF + HS_FLOATS)
#define RED_FLOATS (NKC * 256)                // 4096
#define INS_OFF  (RED_OFF + RED_FLOATS)       // duplicated-pair input stage
#define INS_FLOATS (2 * BPC * IN_DIM * 2)     // 4096 (2 bufs x 4b x 256i x ull)
#define MB_OFF   (INS_OFF + INS_FLOATS)
#define SCAN_SMEM_BYTES  ((MB_OFF + 8) * 4)   // ~180.5 KB

#define TX_BYTES_PER_PHASE (CLS * 256 * 4)    // 8192 B into each CTA per phase

typedef unsigned long long ull;

__device__ __forceinline__ void cluster_sync_() {
    asm volatile("barrier.cluster.arrive.aligned;" ::: "memory");
    asm volatile("barrier.cluster.wait.aligned;"   ::: "memory");
}
__device__ __forceinline__ void mbar_init_(unsigned a, unsigned cnt) {
    asm volatile("mbarrier.init.shared.b64 [%0], %1;" :: "r"(a), "r"(cnt) : "memory");
}
__device__ __forceinline__ void mbar_expect_tx_(unsigned a, unsigned bytes) {
    asm volatile("mbarrier.arrive.expect_tx.shared.b64 _, [%0], %1;"
                 :: "r"(a), "r"(bytes) : "memory");
}
__device__ __forceinline__ void mbar_wait_(unsigned a, unsigned parity) {
    unsigned done;
    asm volatile(
        "{\n\t.reg .pred p;\n\t"
        "mbarrier.try_wait.parity.acquire.cta.shared::cta.b64 p, [%1], %2;\n\t"
        "selp.b32 %0, 1, 0, p;\n\t}"
        : "=r"(done) : "r"(a), "r"(parity) : "memory");
    if (!done) {
        asm volatile(
            "{\n\t.reg .pred P1;\n\t"
            "WL_%=:\n\t"
            "mbarrier.try_wait.parity.acquire.cta.shared::cta.b64 P1, [%0], %1, 0x989680;\n\t"
            "@P1 bra.uni WD_%=;\n\t"
            "bra.uni WL_%=;\n\t"
            "WD_%=:\n\t}"
            :: "r"(a), "r"(parity) : "memory");
    }
}
__device__ __forceinline__ void st_async_f32_(unsigned raddr, float v, unsigned rmbar) {
    asm volatile(
        "st.async.shared::cluster.mbarrier::complete_tx::bytes.b32 [%0], %1, [%2];"
        :: "r"(raddr), "r"(__float_as_int(v)), "r"(rmbar) : "memory");
}
__device__ __forceinline__ ull fma2_(ull a, ull b, ull c) {
    ull d;
    asm("fma.rn.f32x2 %0, %1, %2, %3;" : "=l"(d) : "l"(a), "l"(b), "l"(c));
    return d;
}
__device__ __forceinline__ ull pack2_(float x) {
    ull d;
    asm("mov.b64 %0, {%1, %1};" : "=l"(d) : "r"(__float_as_int(x)));
    return d;
}
__device__ __forceinline__ ull packab_(float lo, float hi) {
    ull d;
    asm("mov.b64 %0, {%1, %2};" : "=l"(d)
        : "r"(__float_as_int(lo)), "r"(__float_as_int(hi)));
    return d;
}

__global__ __launch_bounds__(256, 1) __cluster_dims__(CLS, 1, 1)
void rnn_fused_kernel(const float* __restrict__ input,
                      const float* __restrict__ w_in,
                      const float* __restrict__ w_rec,
                      float* __restrict__ out, int write_last)
{
    extern __shared__ float smem[];
    float* ws   = smem + WS_OFF;   // [HID][JPC]
    float* hs   = smem + HS_OFF;   // [2][BPC][HPAD]
    float* red  = smem + RED_OFF;  // [NKC][256]
    ull*   ins2 = (ull*)(smem + INS_OFF);  // [2][BPC][IN_DIM] duplicated pairs

    const int tid  = threadIdx.x;
    const int rank = blockIdx.x & (CLS - 1);
    const int b0   = (blockIdx.x >> 3) * BPC;
    const int j0   = rank * JPC;

    const int kc = tid >> 4;      // 0..15 chunk (k and i)
    const int jg = tid & 15;      // 0..15 j-group (4 cols)
    const int ob = tid >> 6;      // 0..3 output batch
    const int oj = tid & 63;      // 0..63 output column
    const int sb = tid >> 6;      // staging batch
    const int si = tid & 63;      // staging i/4

    // ---- prologue ----
    {
        const float4* wsrc = (const float4*)w_rec;
        float4* wdst = (float4*)ws;
        for (int i = tid; i < HID * (JPC / 4); i += 256) {
            int row = i >> 4, c4 = i & 15;
            wdst[row * 16 + c4] = wsrc[row * (HID / 4) + (j0 >> 2) + c4];
        }
        for (int i = tid; i < HS_FLOATS; i += 256) hs[i] = 0.0f;
        if (tid == 0) {
            unsigned mb = (unsigned)__cvta_generic_to_shared(smem + MB_OFF);
            mbar_init_(mb, 1);
            mbar_init_(mb + 8, 1);
        }
        // stage input[0] (duplicated pairs, transposed to [b][i])
        float4 v = *(const float4*)&input[((size_t)0 * BATCH + b0 + sb) * IN_DIM + si * 4];
        ull* dst = ins2 + (size_t)0 * BPC * IN_DIM + sb * IN_DIM + si * 4;
        dst[0] = pack2_(v.x); dst[1] = pack2_(v.y);
        dst[2] = pack2_(v.z); dst[3] = pack2_(v.w);
    }

    // w_in slice in registers: wi_[il][cp] = w_in[kc*16+il][j0+jg*4 ..+3]
    ull wi_[IC][2];
#pragma unroll
    for (int il = 0; il < IC; il++) {
        float4 wv = *(const float4*)&w_in[(size_t)(kc * IC + il) * HID + j0 + jg * 4];
        wi_[il][0] = packab_(wv.x, wv.y);
        wi_[il][1] = packab_(wv.z, wv.w);
    }

    __syncthreads();
    cluster_sync_();   // peers' smem + mbarriers live before any st.async

    const unsigned hs_loc = (unsigned)__cvta_generic_to_shared(hs);
    const unsigned mb_loc = (unsigned)__cvta_generic_to_shared(smem + MB_OFF);
    unsigned peer_hs[CLS], peer_mb[CLS];
#pragma unroll
    for (int r = 0; r < CLS; r++) {
        asm("mapa.shared::cluster.u32 %0, %1, %2;" : "=r"(peer_hs[r]) : "r"(hs_loc), "r"(r));
        asm("mapa.shared::cluster.u32 %0, %1, %2;" : "=r"(peer_mb[r]) : "r"(mb_loc), "r"(r));
    }

    const float* wrow = ws + (kc * KC) * JPC + jg * 4;
    const size_t xbase = (size_t)(b0 + ob) * HID + j0 + oj;
    const unsigned st_off_base = (unsigned)((ob * HPAD + j0 + oj) * 4);

    int par0 = 0, par1 = 0;

#pragma unroll 1
    for (int t = 0; t < T_STEPS; t++) {
        const int q  = t & 1;
        const int qn = q ^ 1;

        // prefetch next input slice (independent of the wait)
        float4 nv;
        if (t < T_STEPS - 1)
            nv = *(const float4*)&input[((size_t)(t + 1) * BATCH + b0 + sb) * IN_DIM + si * 4];

        if (t > 0) {
            if (q == 0) { mbar_wait_(mb_loc,     par0); par0 ^= 1; }
            else        { mbar_wait_(mb_loc + 8, par1); par1 ^= 1; }
        }
        if (tid == 0 && t < T_STEPS - 1)
            mbar_expect_tx_(mb_loc + (unsigned)qn * 8, TX_BYTES_PER_PHASE);

        // ---- split-K partials: h@w_rec (32 k) + x@w_in (16 i) ----
        const float* hp = hs + q * BPC * HPAD + kc * KC;
        const ull* ibase = ins2 + (size_t)q * BPC * IN_DIM + kc * IC;

        ull acc2[BPC][2];
#pragma unroll
        for (int b = 0; b < BPC; b++) { acc2[b][0] = 0ull; acc2[b][1] = 0ull; }

#pragma unroll
        for (int ki = 0; ki < KC; ki += 4) {
            ulonglong2 w0 = *(const ulonglong2*)(wrow + (ki + 0) * JPC);
            ulonglong2 w1 = *(const ulonglong2*)(wrow + (ki + 1) * JPC);
            ulonglong2 w2 = *(const ulonglong2*)(wrow + (ki + 2) * JPC);
            ulonglong2 w3 = *(const ulonglong2*)(wrow + (ki + 3) * JPC);
#pragma unroll
            for (int b = 0; b < BPC; b++) {
                float4 h4 = *(const float4*)(hp + b * HPAD + ki);
                acc2[b][0] = fma2_(pack2_(h4.x), w0.x, acc2[b][0]);
                acc2[b][1] = fma2_(pack2_(h4.x), w0.y, acc2[b][1]);
                acc2[b][0] = fma2_(pack2_(h4.y), w1.x, acc2[b][0]);
                acc2[b][1] = fma2_(pack2_(h4.y), w1.y, acc2[b][1]);
                acc2[b][0] = fma2_(pack2_(h4.z), w2.x, acc2[b][0]);
                acc2[b][1] = fma2_(pack2_(h4.z), w2.y, acc2[b][1]);
                acc2[b][0] = fma2_(pack2_(h4.w), w3.x, acc2[b][0]);
                acc2[b][1] = fma2_(pack2_(h4.w), w3.y, acc2[b][1]);
            }
        }
        // x partials (input pairs already duplicated in smem)
#pragma unroll
        for (int b = 0; b < BPC; b++) {
            const ull* ib = ibase + b * IN_DIM;
#pragma unroll
            for (int il = 0; il < IC; il += 2) {
                ulonglong2 h2 = *(const ulonglong2*)(ib + il);
                acc2[b][0] = fma2_(h2.x, wi_[il][0],     acc2[b][0]);
                acc2[b][1] = fma2_(h2.x, wi_[il][1],     acc2[b][1]);
                acc2[b][0] = fma2_(h2.y, wi_[il + 1][0], acc2[b][0]);
                acc2[b][1] = fma2_(h2.y, wi_[il + 1][1], acc2[b][1]);
            }
        }

        // stage input[t+1] into the other buffer (before the sync)
        if (t < T_STEPS - 1) {
            ull* dst = ins2 + (size_t)qn * BPC * IN_DIM + sb * IN_DIM + si * 4;
            dst[0] = pack2_(nv.x); dst[1] = pack2_(nv.y);
            dst[2] = pack2_(nv.z); dst[3] = pack2_(nv.w);
        }

#pragma unroll
        for (int b = 0; b < BPC; b++) {
            float2 p0 = *(float2*)&acc2[b][0];
            float2 p1 = *(float2*)&acc2[b][1];
            *(float4*)&red[kc * 256 + b * 64 + jg * 4] =
                make_float4(p0.x, p0.y, p1.x, p1.y);
        }
        __syncthreads();

        // ---- reduce over 16 chunks (covers x + recurrence), activate ----
        float s = 0.0f;
#pragma unroll
        for (int c = 0; c < NKC; c++) s += red[c * 256 + tid];
        float hn = tanhf(s);

        out[(size_t)t * BH + xbase] = hn;
        if (write_last && t == T_STEPS - 1)
            out[(size_t)T_STEPS * BH + xbase] = hn;

        // ---- broadcast h_{t+1} via st.async ----
        if (t < T_STEPS - 1) {
            unsigned doff = (unsigned)(qn * BPC * HPAD * 4) + st_off_base;
            unsigned moff = (unsigned)qn * 8;
#pragma unroll
            for (int r = 0; r < CLS; r++)
                st_async_f32_(peer_hs[r] + doff, hn, peer_mb[r] + moff);
        }
    }
    cluster_sync_();
}

// ---------------- launch ----------------------------------------------------
extern "C" void kernel_launch(void* const* d_in, const int* in_sizes, int n_in,
                              void* d_out, int out_size)
{
    const float* input = (const float*)d_in[0];   // [T,B,I]
    const float* w_in  = (const float*)d_in[1];   // [I,H]
    const float* w_rec = (const float*)d_in[2];   // [H,H]
    float* out = (float*)d_out;

    int write_last =
        ((size_t)out_size >= (size_t)T_STEPS * BH + (size_t)BH) ? 1 : 0;

    cudaFuncSetAttribute(rnn_fused_kernel,
                         cudaFuncAttributeMaxDynamicSharedMemorySize,
                         SCAN_SMEM_BYTES);

    rnn_fused_kernel<<<BATCH / BPC * CLS, 256, SCAN_SMEM_BYTES>>>(
        input, w_in, w_rec, out, write_last);
}